// round 9
// baseline (speedup 1.0000x reference)
#include <cuda_runtime.h>
#include <cstdint>

// ScaledDotProductAttention: B=4, W=64, H=64, C=256, M=32, D=32, T=8
// out[b,c,w,h] = sum_m v[b,w,h,c,m] * softmax_m( (q[b,w,h,m,:] . k[b,w,h,:]) / T )
//
// R9: persistent kernel, 148 CTAs (1/SM), all input traffic via cp.async.bulk:
//  - 4-slot ring of 32KB v-slices (up to 3 copies in flight per SM)
//  - double-buffered q(32KB)+k(1KB) tiles (contiguous per 8-h tile)
//  - compute reads smem at the LDS crossbar floor; zero LDG in the hot loop.

#define C_DIM 256
#define M_DIM 32
#define D_DIM 32
#define W_DIM 64
#define H_DIM 64
#define HT 8
#define NTILES 2048            // 4*64*(64/HT)
#define GRID 148
#define NVS 4                  // v ring slots

#define VSLICE_BYTES 32768     // C*M*4
#define QTILE_BYTES  32768     // HT*M*D*4 (contiguous in gmem per tile)
#define KTILE_BYTES  1024      // HT*D*4

#define OFF_V    0
#define OFF_Q    (NVS * VSLICE_BYTES)                 // 131072
#define OFF_K    (OFF_Q + 2 * QTILE_BYTES)            // 196608
#define OFF_WTS  (OFF_K + 2 * KTILE_BYTES)            // 198656
#define OFF_RES  (OFF_WTS + HT * M_DIM * 4)           // 199680
#define OFF_MBAR (OFF_RES + C_DIM * (HT + 1) * 4)     // 208896
#define SMEM_TOTAL (OFF_MBAR + 64)                    // 208960

#define MBAR_WAIT(mb, ph) do {                                                   \
    uint32_t _done;                                                              \
    asm volatile("{\n\t.reg .pred p;\n\t"                                        \
        "mbarrier.try_wait.parity.acquire.cta.shared::cta.b64 p, [%1], %2;\n\t"  \
        "selp.b32 %0, 1, 0, p;\n\t}"                                             \
        : "=r"(_done) : "r"(mb), "r"(ph) : "memory");                            \
    while (!_done) {                                                             \
        asm volatile("{\n\t.reg .pred p;\n\t"                                    \
            "mbarrier.try_wait.parity.acquire.cta.shared::cta.b64 p, [%1], %2, 0x989680;\n\t" \
            "selp.b32 %0, 1, 0, p;\n\t}"                                         \
            : "=r"(_done) : "r"(mb), "r"(ph) : "memory");                        \
    }                                                                            \
} while (0)

__device__ __forceinline__ void bulk_copy(uint32_t dst, const void* src,
                                          uint32_t bytes, uint32_t mb)
{
    asm volatile("cp.async.bulk.shared::cta.global.mbarrier::complete_tx::bytes "
                 "[%0], [%1], %2, [%3];"
                 :: "r"(dst), "l"(src), "r"(bytes), "r"(mb) : "memory");
}
__device__ __forceinline__ void expect_tx(uint32_t mb, uint32_t bytes)
{
    asm volatile("mbarrier.arrive.expect_tx.shared.b64 _, [%0], %1;"
                 :: "r"(mb), "r"(bytes) : "memory");
}

__global__ __launch_bounds__(128, 1)
void sdpa_kernel(const float* __restrict__ q,
                 const float* __restrict__ v,
                 const float* __restrict__ k,
                 float* __restrict__ out)
{
    extern __shared__ char smem[];
    float* wts = (float*)(smem + OFF_WTS);       // [hl][m] softmax weights
    float* res = (float*)(smem + OFF_RES);       // [c][hl], pad 9

    uint32_t sb;
    asm("{ .reg .u64 t; cvta.to.shared.u64 t, %1; cvt.u32.u64 %0, t; }"
        : "=r"(sb) : "l"(smem));
    const uint32_t vmb0  = sb + OFF_MBAR;        // 4 v-full barriers
    const uint32_t qkmb0 = sb + OFF_MBAR + 32;   // 2 qk-full barriers

    const int p    = blockIdx.x;                 // persistent CTA id
    const int tid  = threadIdx.x;
    const int lane = tid & 31;
    const int wid  = tid >> 5;
    const int sub  = lane & 7;
    const int grp  = lane >> 3;

    const int nt  = (NTILES - p + GRID - 1) / GRID;   // my tile count (13 or 14)
    const int nsl = nt * HT;                          // my slice count

    // ---------- init barriers ----------
    if (tid == 0) {
        #pragma unroll
        for (int s = 0; s < NVS; ++s)
            asm volatile("mbarrier.init.shared.b64 [%0], 1;" :: "r"(vmb0 + 8 * s) : "memory");
        #pragma unroll
        for (int s = 0; s < 2; ++s)
            asm volatile("mbarrier.init.shared.b64 [%0], 1;" :: "r"(qkmb0 + 8 * s) : "memory");
    }
    __syncthreads();

    // ---------- prologue: fill qk double-buffer + v ring ----------
    if (tid == 0) {
        #pragma unroll
        for (int i = 0; i < 2; ++i) {
            if (i < nt) {
                const long T = p + (long)i * GRID;
                expect_tx(qkmb0 + 8 * i, QTILE_BYTES + KTILE_BYTES);
                bulk_copy(sb + OFF_Q + i * QTILE_BYTES, q + T * (HT * M_DIM * D_DIM),
                          QTILE_BYTES, qkmb0 + 8 * i);
                bulk_copy(sb + OFF_K + i * KTILE_BYTES, k + T * (HT * D_DIM),
                          KTILE_BYTES, qkmb0 + 8 * i);
            }
        }
        #pragma unroll
        for (int j = 0; j < NVS; ++j) {
            if (j < nsl) {
                const long T  = p + (long)(j >> 3) * GRID;
                const long sl = T * HT + (j & 7);
                expect_tx(vmb0 + 8 * j, VSLICE_BYTES);
                bulk_copy(sb + OFF_V + j * VSLICE_BYTES, v + sl * (C_DIM * M_DIM),
                          VSLICE_BYTES, vmb0 + 8 * j);
            }
        }
    }

    const int cbase = wid * 64;

    for (int i = 0; i < nt; ++i) {
        const int T  = p + i * GRID;
        const int b  = T >> 9;
        const int w  = (T >> 3) & 63;
        const int h0 = (T & 7) * HT;

        // ---------- Phase 1: softmax weights from smem q/k tile ----------
        const int qs = i & 1;
        MBAR_WAIT(qkmb0 + 8 * qs, (i >> 1) & 1);
        {
            const float* __restrict__ qb = (const float*)(smem + OFF_Q + qs * QTILE_BYTES);
            const float* __restrict__ kb = (const float*)(smem + OFF_K + qs * KTILE_BYTES);
            #pragma unroll
            for (int ii = 0; ii < 2; ++ii) {
                const int hl = wid * 2 + ii;
                const float4 k4 = *(const float4*)(kb + hl * D_DIM + sub * 4);
                #pragma unroll
                for (int j = 0; j < 8; ++j) {
                    const int m = j * 4 + grp;
                    const float4 q4 = *(const float4*)(qb + (hl * M_DIM + m) * D_DIM + sub * 4);
                    float pp = q4.x * k4.x + q4.y * k4.y + q4.z * k4.z + q4.w * k4.w;
                    pp += __shfl_xor_sync(0xffffffffu, pp, 4);
                    pp += __shfl_xor_sync(0xffffffffu, pp, 2);
                    pp += __shfl_xor_sync(0xffffffffu, pp, 1);
                    if (sub == 0) wts[hl * M_DIM + m] = pp;
                }
                __syncwarp();
                const float logit = wts[hl * M_DIM + lane] * 0.125f;   // 1/T
                float mx = logit;
                #pragma unroll
                for (int o = 16; o; o >>= 1) mx = fmaxf(mx, __shfl_xor_sync(0xffffffffu, mx, o));
                const float e = __expf(logit - mx);
                float s = e;
                #pragma unroll
                for (int o = 16; o; o >>= 1) s += __shfl_xor_sync(0xffffffffu, s, o);
                wts[hl * M_DIM + lane] = e / s;
            }
        }
        __syncthreads();                  // wts ready; qk buffer consumed
        if (tid == 0 && i + 2 < nt) {     // refill qk slot for tile i+2
            const long T2 = p + (long)(i + 2) * GRID;
            expect_tx(qkmb0 + 8 * qs, QTILE_BYTES + KTILE_BYTES);
            bulk_copy(sb + OFF_Q + qs * QTILE_BYTES, q + T2 * (HT * M_DIM * D_DIM),
                      QTILE_BYTES, qkmb0 + 8 * qs);
            bulk_copy(sb + OFF_K + qs * KTILE_BYTES, k + T2 * (HT * D_DIM),
                      KTILE_BYTES, qkmb0 + 8 * qs);
        }

        // ---------- Phase 2: consume v slices from the ring ----------
        for (int hl = 0; hl < HT; ++hl) {
            const int  j  = i * HT + hl;
            const int  st = j & (NVS - 1);
            MBAR_WAIT(vmb0 + 8 * st, (j >> 2) & 1);

            const float* __restrict__ vb = (const float*)(smem + OFF_V + st * VSLICE_BYTES);
            const float4 w4 = *(const float4*)(wts + hl * M_DIM + sub * 4);
            #pragma unroll
            for (int jj = 0; jj < 16; ++jj) {
                const int c = cbase + jj * 4 + grp;
                const float4 v4 = *(const float4*)(vb + c * M_DIM + sub * 4);
                float pp = v4.x * w4.x + v4.y * w4.y + v4.z * w4.z + v4.w * w4.w;
                pp += __shfl_xor_sync(0xffffffffu, pp, 4);
                pp += __shfl_xor_sync(0xffffffffu, pp, 2);
                pp += __shfl_xor_sync(0xffffffffu, pp, 1);
                if (sub == 0) res[c * (HT + 1) + hl] = pp;
            }
            __syncthreads();              // slot st free
            if (tid == 0 && j + NVS < nsl) {
                const long Tn  = p + (long)((j + NVS) >> 3) * GRID;
                const long sln = Tn * HT + ((j + NVS) & 7);
                expect_tx(vmb0 + 8 * st, VSLICE_BYTES);
                bulk_copy(sb + OFF_V + st * VSLICE_BYTES, v + sln * (C_DIM * M_DIM),
                          VSLICE_BYTES, vmb0 + 8 * st);
            }
        }

        // ---------- Phase 3: coalesced transposed writes ----------
        // 256*8 floats = 512 float4; 128 threads -> 4 iterations.
        #pragma unroll
        for (int it = 0; it < 4; ++it) {
            const int jj = it * 128 + tid;
            const int c2 = jj >> 1;             // 0..255
            const int hb = (jj & 1) << 2;       // 0, 4
            const float* r = &res[c2 * (HT + 1) + hb];
            const float4 o4 = make_float4(r[0], r[1], r[2], r[3]);
            const long oidx = (((long)b * C_DIM + c2) * W_DIM + w) * H_DIM + (h0 + hb);
            __stcs((float4*)(out + oidx), o4);
        }
        __syncthreads();                  // res free before next tile overwrites
    }
}

extern "C" void kernel_launch(void* const* d_in, const int* in_sizes, int n_in,
                              void* d_out, int out_size)
{
    // Resolve inputs by element count: q=16,777,216; v=134,217,728; k=524,288
    const float* q = nullptr;
    const float* v = nullptr;
    const float* k = nullptr;
    for (int i = 0; i < n_in; ++i) {
        if (in_sizes[i] == 16777216)       q = (const float*)d_in[i];
        else if (in_sizes[i] == 134217728) v = (const float*)d_in[i];
        else if (in_sizes[i] == 524288)    k = (const float*)d_in[i];
    }
    float* out = (float*)d_out;

    cudaFuncSetAttribute(sdpa_kernel, cudaFuncAttributeMaxDynamicSharedMemorySize, SMEM_TOTAL);
    sdpa_kernel<<<GRID, 128, SMEM_TOTAL>>>(q, v, k, out);
}

// round 10
// speedup vs baseline: 1.8204x; 1.8204x over previous
#include <cuda_runtime.h>

// ScaledDotProductAttention: B=4, W=64, H=64, C=256, M=32, D=32, T=8
// out[b,c,w,h] = sum_m v[b,w,h,c,m] * softmax_m( (q[b,w,h,m,:] . k[b,w,h,:]) / T )
//
// Pure HBM-streaming kernel (594 MB moved once).
// R3 (90.6us, DRAM 85.8%): coalesced 512B warp loads + shfl reductions,
//     HT=16, 128 thr, occ 8, 1024 CTAs = single wave.
// R4-R9 (all reverted): occupancy/reg/256-bit/bulk-pipeline experiments all
//     regressed or neutral -> LDG streaming at occ 8 is the right structure.
// R10: R3/R6 + per-warp hl rotation in phase 2: the CTA's 4 warps stream 4
//     different 32KB v-slices concurrently (more DRAM row/bank parallelism,
//     less correlated L1tex bursting). Single-variable change vs R6.

#define C_DIM 256
#define M_DIM 32
#define D_DIM 32
#define W_DIM 64
#define H_DIM 64
#define HT 16          // h-tile per CTA

__global__ __launch_bounds__(128, 8)
void sdpa_kernel(const float* __restrict__ q,
                 const float* __restrict__ v,
                 const float* __restrict__ k,
                 float* __restrict__ out)
{
    __shared__ float wts[HT * M_DIM];        // [h_local][m] softmax weights, 2 KB
    __shared__ float res[C_DIM * (HT + 1)];  // [c][h_local], +1 pad, 17.4 KB

    const int hq = blockIdx.x;               // 0..3  (h-tile index)
    const int w  = blockIdx.y;               // 0..63
    const int b  = blockIdx.z;               // 0..3
    const int h0 = hq * HT;

    const int tid  = threadIdx.x;
    const int lane = tid & 31;
    const int wid  = tid >> 5;               // 0..3
    const int sub  = lane & 7;               // position within 8-lane group
    const int grp  = lane >> 3;              // which of 4 groups

    const long slice0 = ((long)(b * W_DIM + w) * H_DIM + h0);

    // ---------- Phase 1: softmax weights; warp wid owns slices wid*4 .. wid*4+3 ----------
    #pragma unroll
    for (int i = 0; i < 4; ++i) {
        const int  hl = wid * 4 + i;
        const long sl = slice0 + hl;

        const float4 k4 = *(const float4*)(k + sl * D_DIM + sub * 4);

        #pragma unroll
        for (int j = 0; j < 8; ++j) {
            const int m = j * 4 + grp;
            const float4 q4 = *(const float4*)(q + (sl * M_DIM + m) * D_DIM + sub * 4);
            float p = q4.x * k4.x + q4.y * k4.y + q4.z * k4.z + q4.w * k4.w;
            p += __shfl_xor_sync(0xffffffffu, p, 4);
            p += __shfl_xor_sync(0xffffffffu, p, 2);
            p += __shfl_xor_sync(0xffffffffu, p, 1);
            if (sub == 0) wts[hl * M_DIM + m] = p;   // raw logit
        }
        __syncwarp();

        const float logit = wts[hl * M_DIM + lane] * 0.125f;  // 1/TEMPERATURE
        float mx = logit;
        #pragma unroll
        for (int o = 16; o; o >>= 1) mx = fmaxf(mx, __shfl_xor_sync(0xffffffffu, mx, o));
        const float e = __expf(logit - mx);
        float s = e;
        #pragma unroll
        for (int o = 16; o; o >>= 1) s += __shfl_xor_sync(0xffffffffu, s, o);
        wts[hl * M_DIM + lane] = e / s;
    }
    __syncthreads();

    // ---------- Phase 2: stream v; warp owns 64 c-values, warps rotated across slices ----------
    const int cbase = wid * 64;
    for (int t = 0; t < HT; ++t) {
        const int hl = (t + wid * 4) & (HT - 1);    // decorrelate the 4 warps
        const float4 w4 = *(const float4*)(wts + hl * M_DIM + sub * 4);
        const float* __restrict__ vbase = v + (slice0 + hl) * (long)(C_DIM * M_DIM);
        #pragma unroll
        for (int j = 0; j < 16; ++j) {
            const int c = cbase + j * 4 + grp;
            const float4 v4 = __ldcs((const float4*)(vbase + c * M_DIM + sub * 4));
            float p = v4.x * w4.x + v4.y * w4.y + v4.z * w4.z + v4.w * w4.w;
            p += __shfl_xor_sync(0xffffffffu, p, 4);
            p += __shfl_xor_sync(0xffffffffu, p, 2);
            p += __shfl_xor_sync(0xffffffffu, p, 1);
            if (sub == 0) res[c * (HT + 1) + hl] = p;
        }
    }
    __syncthreads();

    // ---------- Phase 3: coalesced transposed writes: out[((b*C + c)*W + w)*H + h] ----------
    // 256*16 floats = 1024 float4; 128 threads -> 8 iterations. Streaming stores.
    #pragma unroll
    for (int it = 0; it < 8; ++it) {
        const int j  = it * 128 + tid;
        const int c2 = j >> 2;            // 0..255
        const int hb = (j & 3) << 2;      // 0,4,8,12
        const float* r = &res[c2 * (HT + 1) + hb];
        const float4 o4 = make_float4(r[0], r[1], r[2], r[3]);
        const long oidx = (((long)b * C_DIM + c2) * W_DIM + w) * H_DIM + (h0 + hb);
        __stcs((float4*)(out + oidx), o4);
    }
}

extern "C" void kernel_launch(void* const* d_in, const int* in_sizes, int n_in,
                              void* d_out, int out_size)
{
    // Resolve inputs by element count: q=16,777,216; v=134,217,728; k=524,288
    const float* q = nullptr;
    const float* v = nullptr;
    const float* k = nullptr;
    for (int i = 0; i < n_in; ++i) {
        if (in_sizes[i] == 16777216)       q = (const float*)d_in[i];
        else if (in_sizes[i] == 134217728) v = (const float*)d_in[i];
        else if (in_sizes[i] == 524288)    k = (const float*)d_in[i];
    }
    float* out = (float*)d_out;

    dim3 grid(H_DIM / HT, W_DIM, 4);   // (4, 64, 4) = 1024 CTAs
    sdpa_kernel<<<grid, 128>>>(q, v, k, out);
}